// round 1
// baseline (speedup 1.0000x reference)
#include <cuda_runtime.h>
#include <math.h>

#define BATCH 8
#define TSTEPS 2048
#define DIM 1024
#define MM (BATCH * TSTEPS)   // 16384 rows
#define NN 1024
#define KK 1024
#define EPS 1e-6f

// Scratch (device globals — allocation-free per harness rules)
__device__ float g_buf_xp[(size_t)MM * NN];  // xp, later reused as outs
__device__ float g_buf_wx[(size_t)MM * NN];  // Wx

// ---------------------------------------------------------------------------
// GEMM: C[M,N] = epilogue(A[M,K] @ W[N,K]^T)
// MODE 0: silu(v)   MODE 1: v + bias[col]   MODE 2: v
// BM=BN=128, BK=8, 256 threads, 8x8 per-thread tile.
// ---------------------------------------------------------------------------
template <int MODE>
__global__ __launch_bounds__(256, 2)
void gemm_kernel(const float* __restrict__ A,
                 const float* __restrict__ W,
                 const float* __restrict__ bias,
                 float* __restrict__ C)
{
    const int BM = 128, BN = 128, BK = 8;
    __shared__ float As[BK][BM];
    __shared__ float Ws[BK][BN];

    const int tid = threadIdx.x;          // 0..255
    const int bm  = blockIdx.y * BM;
    const int bn  = blockIdx.x * BN;

    const int tn = tid & 15;              // 0..15
    const int tm = tid >> 4;              // 0..15

    // Load mapping: one float4 per thread per tile for each of A, W
    const int ldrow = tid >> 1;           // 0..127
    const int ldk   = (tid & 1) * 4;      // 0 or 4

    float acc[8][8];
#pragma unroll
    for (int i = 0; i < 8; i++)
#pragma unroll
        for (int j = 0; j < 8; j++) acc[i][j] = 0.f;

    const float* Aptr = A + (size_t)(bm + ldrow) * KK + ldk;
    const float* Wptr = W + (size_t)(bn + ldrow) * KK + ldk;

    for (int k0 = 0; k0 < KK; k0 += BK) {
        float4 a = *(const float4*)(Aptr + k0);
        float4 w = *(const float4*)(Wptr + k0);
        As[ldk + 0][ldrow] = a.x; As[ldk + 1][ldrow] = a.y;
        As[ldk + 2][ldrow] = a.z; As[ldk + 3][ldrow] = a.w;
        Ws[ldk + 0][ldrow] = w.x; Ws[ldk + 1][ldrow] = w.y;
        Ws[ldk + 2][ldrow] = w.z; Ws[ldk + 3][ldrow] = w.w;
        __syncthreads();

#pragma unroll
        for (int k = 0; k < BK; k++) {
            float af[8], bf[8];
            *(float4*)&af[0] = *(const float4*)&As[k][tm * 8];
            *(float4*)&af[4] = *(const float4*)&As[k][tm * 8 + 4];
            *(float4*)&bf[0] = *(const float4*)&Ws[k][tn * 8];
            *(float4*)&bf[4] = *(const float4*)&Ws[k][tn * 8 + 4];
#pragma unroll
            for (int i = 0; i < 8; i++)
#pragma unroll
                for (int j = 0; j < 8; j++)
                    acc[i][j] = fmaf(af[i], bf[j], acc[i][j]);
        }
        __syncthreads();
    }

    // Epilogue
    float bvals[8];
    if (MODE == 1) {
#pragma unroll
        for (int j = 0; j < 8; j++) bvals[j] = bias[bn + tn * 8 + j];
    }
#pragma unroll
    for (int i = 0; i < 8; i++) {
        const int row = bm + tm * 8 + i;
        float out[8];
#pragma unroll
        for (int j = 0; j < 8; j++) {
            float v = acc[i][j];
            if (MODE == 0) v = v / (1.f + __expf(-v));   // silu
            if (MODE == 1) v = v + bvals[j];
            out[j] = v;
        }
        float* cp = C + (size_t)row * NN + bn + tn * 8;
        *(float4*)(cp)     = *(float4*)&out[0];
        *(float4*)(cp + 4) = *(float4*)&out[4];
    }
}

// ---------------------------------------------------------------------------
// Sequential scan: one block per batch (8 blocks, 256 threads, 4 elems/thread).
// h kept in registers. Double-buffered smem reduction -> one barrier per step.
// Next step's wx prefetched before the reduction.
// ---------------------------------------------------------------------------
__global__ __launch_bounds__(256, 1)
void scan_kernel(const float* __restrict__ Wx,
                 const float* __restrict__ h0,
                 const float* __restrict__ log_alpha,
                 float* __restrict__ outs,
                 float* __restrict__ h_final)
{
    const int b    = blockIdx.x;      // 0..7
    const int tid  = threadIdx.x;     // 0..255
    const int lane = tid & 31;
    const int warp = tid >> 5;        // 0..7

    __shared__ float red[2][8];

    const float alpha = __expf(log_alpha[0]);

    float4 h = *(const float4*)(h0 + (size_t)b * DIM + tid * 4);

    const float* wxb = Wx   + (size_t)b * TSTEPS * DIM;
    float*       ob  = outs + (size_t)b * TSTEPS * DIM;

    float4 wx = *(const float4*)(wxb + tid * 4);

    for (int t = 0; t < TSTEPS; t++) {
        float4 wxn = make_float4(0.f, 0.f, 0.f, 0.f);
        if (t + 1 < TSTEPS)
            wxn = *(const float4*)(wxb + (size_t)(t + 1) * DIM + tid * 4);

        h.x = fmaf(alpha, wx.x, h.x);
        h.y = fmaf(alpha, wx.y, h.y);
        h.z = fmaf(alpha, wx.z, h.z);
        h.w = fmaf(alpha, wx.w, h.w);

        float ss = h.x * h.x + h.y * h.y + h.z * h.z + h.w * h.w;
#pragma unroll
        for (int off = 16; off > 0; off >>= 1)
            ss += __shfl_xor_sync(0xffffffffu, ss, off);
        if (lane == 0) red[t & 1][warp] = ss;
        __syncthreads();

        float tot = 0.f;
#pragma unroll
        for (int w = 0; w < 8; w++) tot += red[t & 1][w];

        const float rstd = rsqrtf(tot * (1.0f / DIM) + EPS);
        h.x *= rstd; h.y *= rstd; h.z *= rstd; h.w *= rstd;

        float4 o;
        o.x = h.x * h.x / (1.f + __expf(-h.x));
        o.y = h.y * h.y / (1.f + __expf(-h.y));
        o.z = h.z * h.z / (1.f + __expf(-h.z));
        o.w = h.w * h.w / (1.f + __expf(-h.w));
        *(float4*)(ob + (size_t)t * DIM + tid * 4) = o;

        wx = wxn;
    }

    if (h_final)
        *(float4*)(h_final + (size_t)b * DIM + tid * 4) = h;
}

// ---------------------------------------------------------------------------
extern "C" void kernel_launch(void* const* d_in, const int* in_sizes, int n_in,
                              void* d_out, int out_size)
{
    const float* x         = (const float*)d_in[0];  // [8,2048,1024]
    const float* h0        = (const float*)d_in[1];  // [8,1024]
    const float* W_in      = (const float*)d_in[2];  // [1024,1024]
    const float* W_cell    = (const float*)d_in[3];  // [1024,1024]
    const float* b_cell    = (const float*)d_in[4];  // [1024]
    const float* log_alpha = (const float*)d_in[5];  // [1]
    const float* W_out     = (const float*)d_in[6];  // [1024,1024]

    float* y = (float*)d_out;
    float* h_final = nullptr;
    if ((size_t)out_size >= (size_t)MM * DIM + (size_t)BATCH * DIM)
        h_final = y + (size_t)MM * DIM;

    float *xp = nullptr, *wx = nullptr;
    cudaGetSymbolAddress((void**)&xp, g_buf_xp);
    cudaGetSymbolAddress((void**)&wx, g_buf_wx);

    dim3 grid(NN / 128, MM / 128);
    dim3 block(256);

    // GEMM1: xp = silu(x @ W_in^T)
    gemm_kernel<0><<<grid, block>>>(x, W_in, nullptr, xp);
    // GEMM2: Wx = xp @ W_cell^T + b_cell
    gemm_kernel<1><<<grid, block>>>(xp, W_cell, b_cell, wx);
    // Scan: outs (reusing xp buffer), h_final
    scan_kernel<<<BATCH, 256>>>(wx, h0, log_alpha, xp, h_final);
    // GEMM3: y = outs @ W_out^T
    gemm_kernel<2><<<grid, block>>>(xp, W_out, nullptr, y);
}

// round 4
// speedup vs baseline: 1.3883x; 1.3883x over previous
#include <cuda_runtime.h>
#include <cuda_bf16.h>
#include <mma.h>
#include <math.h>

using namespace nvcuda;

#define BATCH 8
#define TSTEPS 2048
#define DIM 1024
#define MM (BATCH * TSTEPS)   // 16384 rows
#define NN 1024
#define KK 1024
#define EPS 1e-6f

// Scratch (device globals — allocation-free per harness rules)
__device__ float g_buf_xp[(size_t)MM * NN];  // xp, later reused as outs
__device__ float g_buf_wx[(size_t)MM * NN];  // alpha*Wx + alpha*b

// ---------------------------------------------------------------------------
// Tensor-core GEMM (bf16 3-pass split for fp32-level accuracy):
//   C[M,N] = epilogue(A[M,K] @ W[N,K]^T)
// MODE 0: silu(v)    MODE 1: alpha*(v + bias[n])    MODE 2: v
// BM=BN=128, BK=32, 256 threads (8 warps), warp tile 64x32 via wmma 16x16x16.
// ---------------------------------------------------------------------------
#define BM 128
#define BN 128
#define BK 32
#define LDT 40   // smem tile leading dim (bf16 elems); 80B rows, 16B-multiple

template <int MODE>
__global__ __launch_bounds__(256, 1)
void gemm_tc(const float* __restrict__ A,
             const float* __restrict__ W,
             const float* __restrict__ bias,
             const float* __restrict__ log_alpha,
             float* __restrict__ C)
{
    // 4 bf16 tiles of 128 x LDT: 4 * 128*40*2 = 40960 bytes
    __shared__ __align__(32) char smraw[4 * BM * LDT * 2];
    __nv_bfloat16* Ah = (__nv_bfloat16*)smraw;
    __nv_bfloat16* Al = Ah + BM * LDT;
    __nv_bfloat16* Bh = Al + BM * LDT;
    __nv_bfloat16* Bl = Bh + BM * LDT;

    const int tid  = threadIdx.x;
    const int wid  = tid >> 5;
    const int lane = tid & 31;
    const int bm   = blockIdx.y * BM;
    const int bn   = blockIdx.x * BN;

    const int wm = wid & 1;   // 0..1  -> 64-row slab
    const int wn = wid >> 1;  // 0..3  -> 32-col slab

    // Load mapping: row = tid>>1 (0..127), half = tid&1 -> 16 consecutive k
    const int ldrow  = tid >> 1;
    const int ldcol0 = (tid & 1) * 16;

    const float* Aptr = A + (size_t)(bm + ldrow) * KK + ldcol0;
    const float* Wptr = W + (size_t)(bn + ldrow) * KK + ldcol0;

    wmma::fragment<wmma::accumulator, 16, 16, 16, float> acc[4][2];
#pragma unroll
    for (int i = 0; i < 4; i++)
#pragma unroll
        for (int j = 0; j < 2; j++) wmma::fill_fragment(acc[i][j], 0.0f);

    for (int k0 = 0; k0 < KK; k0 += BK) {
        // ---- load + hi/lo split into smem ----
#pragma unroll
        for (int j = 0; j < 4; j++) {
            float4 a = *(const float4*)(Aptr + k0 + j * 4);
            float4 w = *(const float4*)(Wptr + k0 + j * 4);
            const int off = ldrow * LDT + ldcol0 + j * 4;
            float av[4] = {a.x, a.y, a.z, a.w};
            float wv[4] = {w.x, w.y, w.z, w.w};
#pragma unroll
            for (int q = 0; q < 4; q++) {
                __nv_bfloat16 ah = __float2bfloat16(av[q]);
                __nv_bfloat16 al = __float2bfloat16(av[q] - __bfloat162float(ah));
                __nv_bfloat16 wh = __float2bfloat16(wv[q]);
                __nv_bfloat16 wl = __float2bfloat16(wv[q] - __bfloat162float(wh));
                Ah[off + q] = ah; Al[off + q] = al;
                Bh[off + q] = wh; Bl[off + q] = wl;
            }
        }
        __syncthreads();

        // ---- tensor-core compute: 2 k-steps of 16 ----
#pragma unroll
        for (int ks = 0; ks < BK; ks += 16) {
            wmma::fragment<wmma::matrix_a, 16, 16, 16, __nv_bfloat16, wmma::row_major> fah[4], fal[4];
            wmma::fragment<wmma::matrix_b, 16, 16, 16, __nv_bfloat16, wmma::col_major> fbh[2], fbl[2];
#pragma unroll
            for (int i = 0; i < 4; i++) {
                const int row = wm * 64 + i * 16;
                wmma::load_matrix_sync(fah[i], Ah + row * LDT + ks, LDT);
                wmma::load_matrix_sync(fal[i], Al + row * LDT + ks, LDT);
            }
#pragma unroll
            for (int j = 0; j < 2; j++) {
                const int col = wn * 32 + j * 16;
                wmma::load_matrix_sync(fbh[j], Bh + col * LDT + ks, LDT);
                wmma::load_matrix_sync(fbl[j], Bl + col * LDT + ks, LDT);
            }
#pragma unroll
            for (int i = 0; i < 4; i++)
#pragma unroll
                for (int j = 0; j < 2; j++) {
                    wmma::mma_sync(acc[i][j], fah[i], fbl[j], acc[i][j]);
                    wmma::mma_sync(acc[i][j], fal[i], fbh[j], acc[i][j]);
                    wmma::mma_sync(acc[i][j], fah[i], fbh[j], acc[i][j]);
                }
        }
        __syncthreads();
    }

    // ---- epilogue via per-warp smem staging (reuses tile smem; all reads done) ----
    float aval = 0.f;
    if (MODE == 1) aval = __expf(log_alpha[0]);
    float* stage = (float*)smraw + wid * 256;  // 16x16 per warp

    const int r = lane >> 1;            // 0..15
    const int c0 = (lane & 1) * 8;      // 0 or 8
#pragma unroll
    for (int i = 0; i < 4; i++) {
#pragma unroll
        for (int j = 0; j < 2; j++) {
            wmma::store_matrix_sync(stage, acc[i][j], 16, wmma::mem_row_major);
            __syncwarp();
            const int grow = bm + wm * 64 + i * 16 + r;
            const int gcol = bn + wn * 32 + j * 16 + c0;
            float v[8];
            *(float4*)&v[0] = *(float4*)&stage[r * 16 + c0];
            *(float4*)&v[4] = *(float4*)&stage[r * 16 + c0 + 4];
#pragma unroll
            for (int q = 0; q < 8; q++) {
                float t = v[q];
                if (MODE == 0) t = t / (1.f + __expf(-t));           // silu
                if (MODE == 1) t = aval * (t + bias[gcol + q]);      // alpha*(v+b)
                v[q] = t;
            }
            float* cp = C + (size_t)grow * NN + gcol;
            *(float4*)(cp)     = *(float4*)&v[0];
            *(float4*)(cp + 4) = *(float4*)&v[4];
            __syncwarp();
        }
    }
}

// ---------------------------------------------------------------------------
// Sequential scan: one block per batch (8 blocks, 256 threads, 4 elems/thread).
// Wx already scaled by alpha (folded into GEMM2 epilogue).
// Prefetch distance 2, branch-free clamped index.
// ---------------------------------------------------------------------------
__global__ __launch_bounds__(256, 1)
void scan_kernel(const float* __restrict__ Wx,
                 const float* __restrict__ h0,
                 float* __restrict__ outs,
                 float* __restrict__ h_final)
{
    const int b    = blockIdx.x;
    const int tid  = threadIdx.x;
    const int lane = tid & 31;
    const int warp = tid >> 5;

    __shared__ float red[2][8];

    float4 h = *(const float4*)(h0 + (size_t)b * DIM + tid * 4);

    const float* wxb = Wx   + (size_t)b * TSTEPS * DIM;
    float*       ob  = outs + (size_t)b * TSTEPS * DIM;

    float4 wx0 = *(const float4*)(wxb + (size_t)0 * DIM + tid * 4);
    float4 wx1 = *(const float4*)(wxb + (size_t)1 * DIM + tid * 4);

    for (int t = 0; t < TSTEPS; t++) {
        const int tn = (t + 2 < TSTEPS) ? (t + 2) : (TSTEPS - 1);
        float4 wxn = *(const float4*)(wxb + (size_t)tn * DIM + tid * 4);

        h.x += wx0.x; h.y += wx0.y; h.z += wx0.z; h.w += wx0.w;

        float ss = h.x * h.x;
        ss = fmaf(h.y, h.y, ss);
        ss = fmaf(h.z, h.z, ss);
        ss = fmaf(h.w, h.w, ss);
#pragma unroll
        for (int off = 16; off > 0; off >>= 1)
            ss += __shfl_xor_sync(0xffffffffu, ss, off);
        if (lane == 0) red[t & 1][warp] = ss;
        __syncthreads();

        float tot = (red[t & 1][0] + red[t & 1][1]) + (red[t & 1][2] + red[t & 1][3]);
        tot += (red[t & 1][4] + red[t & 1][5]) + (red[t & 1][6] + red[t & 1][7]);

        const float rstd = rsqrtf(tot * (1.0f / DIM) + EPS);
        h.x *= rstd; h.y *= rstd; h.z *= rstd; h.w *= rstd;

        float4 o;
        o.x = h.x * h.x / (1.f + __expf(-h.x));
        o.y = h.y * h.y / (1.f + __expf(-h.y));
        o.z = h.z * h.z / (1.f + __expf(-h.z));
        o.w = h.w * h.w / (1.f + __expf(-h.w));
        *(float4*)(ob + (size_t)t * DIM + tid * 4) = o;

        wx0 = wx1;
        wx1 = wxn;
    }

    if (h_final)
        *(float4*)(h_final + (size_t)b * DIM + tid * 4) = h;
}

// ---------------------------------------------------------------------------
extern "C" void kernel_launch(void* const* d_in, const int* in_sizes, int n_in,
                              void* d_out, int out_size)
{
    const float* x         = (const float*)d_in[0];  // [8,2048,1024]
    const float* h0        = (const float*)d_in[1];  // [8,1024]
    const float* W_in      = (const float*)d_in[2];  // [1024,1024]
    const float* W_cell    = (const float*)d_in[3];  // [1024,1024]
    const float* b_cell    = (const float*)d_in[4];  // [1024]
    const float* log_alpha = (const float*)d_in[5];  // [1]
    const float* W_out     = (const float*)d_in[6];  // [1024,1024]

    float* y = (float*)d_out;
    float* h_final = nullptr;
    if ((size_t)out_size >= (size_t)MM * DIM + (size_t)BATCH * DIM)
        h_final = y + (size_t)MM * DIM;

    float *xp = nullptr, *wx = nullptr;
    cudaGetSymbolAddress((void**)&xp, g_buf_xp);
    cudaGetSymbolAddress((void**)&wx, g_buf_wx);

    dim3 grid(NN / BN, MM / BM);
    dim3 block(256);

    // GEMM1: xp = silu(x @ W_in^T)
    gemm_tc<0><<<grid, block>>>(x, W_in, nullptr, nullptr, xp);
    // GEMM2: wx = alpha*(xp @ W_cell^T + b_cell)
    gemm_tc<1><<<grid, block>>>(xp, W_cell, b_cell, log_alpha, wx);
    // Scan: outs (reusing xp buffer), h_final
    scan_kernel<<<BATCH, 256>>>(wx, h0, xp, h_final);
    // GEMM3: y = outs @ W_out^T
    gemm_tc<2><<<grid, block>>>(xp, W_out, nullptr, nullptr, y);
}

// round 5
// speedup vs baseline: 1.7236x; 1.2415x over previous
#include <cuda_runtime.h>
#include <cuda_bf16.h>
#include <mma.h>
#include <math.h>
#include <stdint.h>

using namespace nvcuda;

#define BATCH 8
#define TSTEPS 2048
#define DIM 1024
#define MM (BATCH * TSTEPS)   // 16384 rows
#define NN 1024
#define KK 1024
#define EPS 1e-6f

// ---------------- device-global scratch (allocation-free) -------------------
__device__ float         g_wx [(size_t)MM * NN];   // fp32 scan input
__device__ __nv_bfloat16 g_xh [(size_t)MM * KK], g_xl [(size_t)MM * KK];   // split(x)
__device__ __nv_bfloat16 g_aph[(size_t)MM * KK], g_apl[(size_t)MM * KK];   // split(xp)
__device__ __nv_bfloat16 g_oh [(size_t)MM * KK], g_ol [(size_t)MM * KK];   // split(outs)
__device__ __nv_bfloat16 g_wih[(size_t)NN * KK], g_wil[(size_t)NN * KK];
__device__ __nv_bfloat16 g_wch[(size_t)NN * KK], g_wcl[(size_t)NN * KK];
__device__ __nv_bfloat16 g_woh[(size_t)NN * KK], g_wol[(size_t)NN * KK];

// ---------------- fp32 -> bf16 hi/lo split (one-time) -----------------------
__global__ void split_fp32(const float* __restrict__ s,
                           __nv_bfloat16* __restrict__ hi,
                           __nv_bfloat16* __restrict__ lo, int n8)
{
    int i = blockIdx.x * blockDim.x + threadIdx.x;
    if (i >= n8) return;
    const float4* p = (const float4*)s + (size_t)i * 2;
    float4 a = p[0], b = p[1];
    float v[8] = {a.x, a.y, a.z, a.w, b.x, b.y, b.z, b.w};
    __align__(16) __nv_bfloat16 h[8], l[8];
#pragma unroll
    for (int q = 0; q < 8; q++) {
        h[q] = __float2bfloat16(v[q]);
        l[q] = __float2bfloat16(v[q] - __bfloat162float(h[q]));
    }
    *(uint4*)(hi + (size_t)i * 8) = *(uint4*)h;
    *(uint4*)(lo + (size_t)i * 8) = *(uint4*)l;
}

// ---------------- cp.async helpers ------------------------------------------
__device__ __forceinline__ void cp_async_16(void* smem, const void* gmem)
{
    uint32_t s = (uint32_t)__cvta_generic_to_shared(smem);
    asm volatile("cp.async.ca.shared.global [%0], [%1], 16;\n" :: "r"(s), "l"(gmem));
}
__device__ __forceinline__ void cp_commit()
{
    asm volatile("cp.async.commit_group;\n" ::: "memory");
}
template <int N>
__device__ __forceinline__ void cp_wait()
{
    asm volatile("cp.async.wait_group %0;\n" :: "n"(N) : "memory");
}

// ---------------- pipelined bf16 3-pass GEMM --------------------------------
//   C[M,N] = epilogue(A @ B^T),  A = Ah+Al, B = Bh+Bl (bf16 planes)
// MODE 0: silu -> bf16 hi/lo planes     (GEMM1)
// MODE 1: alpha*(v+bias) -> fp32        (GEMM2)
// MODE 2: v -> fp32                     (GEMM3)
#define BM 128
#define BN 128
#define BK 32
#define LDT 40                       // smem row stride in bf16 elems (80B)
#define QUAD (BM * LDT * 2)          // 10240 B per quadrant tile
#define STAGE_BYTES (4 * QUAD)       // 40960 B
#define STAGES 3
#define GEMM_SMEM (STAGES * STAGE_BYTES)

__device__ __forceinline__ void load_quad(const __nv_bfloat16* __restrict__ gplane,
                                          int grow0, int k0, char* sq, int tid)
{
#pragma unroll
    for (int i = 0; i < 2; i++) {
        int c   = tid + i * 256;       // 0..511
        int row = c >> 2;              // 0..127
        int cb  = c & 3;               // 16B chunk within 64B row
        const __nv_bfloat16* g = gplane + (size_t)(grow0 + row) * KK + k0 + cb * 8;
        cp_async_16(sq + row * (LDT * 2) + cb * 16, g);
    }
}

template <int MODE>
__global__ __launch_bounds__(256, 1)
void gemm_bf16(const __nv_bfloat16* __restrict__ Ah_, const __nv_bfloat16* __restrict__ Al_,
               const __nv_bfloat16* __restrict__ Bh_, const __nv_bfloat16* __restrict__ Bl_,
               const float* __restrict__ bias, const float* __restrict__ log_alpha,
               float* __restrict__ Cf,
               __nv_bfloat16* __restrict__ Ch, __nv_bfloat16* __restrict__ Cl)
{
    extern __shared__ __align__(16) char dsm[];

    const int tid  = threadIdx.x;
    const int wid  = tid >> 5;
    const int lane = tid & 31;
    const int bm   = blockIdx.y * BM;
    const int bn   = blockIdx.x * BN;

    const int wm = wid & 1;   // 64-row slab
    const int wn = wid >> 1;  // 32-col slab

    wmma::fragment<wmma::accumulator, 16, 16, 16, float> acc[4][2];
#pragma unroll
    for (int i = 0; i < 4; i++)
#pragma unroll
        for (int j = 0; j < 2; j++) wmma::fill_fragment(acc[i][j], 0.0f);

    const int NT = KK / BK;   // 32 tiles

    // prologue: stages 0..STAGES-2
#pragma unroll
    for (int s = 0; s < STAGES - 1; s++) {
        char* p = dsm + s * STAGE_BYTES;
        load_quad(Ah_, bm, s * BK, p,            tid);
        load_quad(Al_, bm, s * BK, p + QUAD,     tid);
        load_quad(Bh_, bn, s * BK, p + 2 * QUAD, tid);
        load_quad(Bl_, bn, s * BK, p + 3 * QUAD, tid);
        cp_commit();
    }

    for (int t = 0; t < NT; t++) {
        cp_wait<STAGES - 2>();
        __syncthreads();

        char* p = dsm + (t % STAGES) * STAGE_BYTES;
        const __nv_bfloat16* Ah = (const __nv_bfloat16*)p;
        const __nv_bfloat16* Al = (const __nv_bfloat16*)(p + QUAD);
        const __nv_bfloat16* Bh = (const __nv_bfloat16*)(p + 2 * QUAD);
        const __nv_bfloat16* Bl = (const __nv_bfloat16*)(p + 3 * QUAD);

#pragma unroll
        for (int ks = 0; ks < BK; ks += 16) {
            wmma::fragment<wmma::matrix_a, 16, 16, 16, __nv_bfloat16, wmma::row_major> fah[4], fal[4];
            wmma::fragment<wmma::matrix_b, 16, 16, 16, __nv_bfloat16, wmma::col_major> fbh[2], fbl[2];
#pragma unroll
            for (int i = 0; i < 4; i++) {
                const int row = wm * 64 + i * 16;
                wmma::load_matrix_sync(fah[i], Ah + row * LDT + ks, LDT);
                wmma::load_matrix_sync(fal[i], Al + row * LDT + ks, LDT);
            }
#pragma unroll
            for (int j = 0; j < 2; j++) {
                const int col = wn * 32 + j * 16;
                wmma::load_matrix_sync(fbh[j], Bh + col * LDT + ks, LDT);
                wmma::load_matrix_sync(fbl[j], Bl + col * LDT + ks, LDT);
            }
#pragma unroll
            for (int i = 0; i < 4; i++)
#pragma unroll
                for (int j = 0; j < 2; j++) {
                    wmma::mma_sync(acc[i][j], fah[i], fbl[j], acc[i][j]);
                    wmma::mma_sync(acc[i][j], fal[i], fbh[j], acc[i][j]);
                    wmma::mma_sync(acc[i][j], fah[i], fbh[j], acc[i][j]);
                }
        }

        // refill the stage freed at iter t-1
        if (t + STAGES - 1 < NT) {
            const int tn = t + STAGES - 1;
            char* pn = dsm + (tn % STAGES) * STAGE_BYTES;
            load_quad(Ah_, bm, tn * BK, pn,            tid);
            load_quad(Al_, bm, tn * BK, pn + QUAD,     tid);
            load_quad(Bh_, bn, tn * BK, pn + 2 * QUAD, tid);
            load_quad(Bl_, bn, tn * BK, pn + 3 * QUAD, tid);
        }
        cp_commit();
    }
    __syncthreads();

    // ---- epilogue: per-warp smem staging ----
    float aval = 0.f;
    if (MODE == 1) aval = __expf(log_alpha[0]);
    float* stage = (float*)dsm + wid * 256;   // 16x16 fp32 per warp

    const int r  = lane >> 1;
    const int c0 = (lane & 1) * 8;
#pragma unroll
    for (int i = 0; i < 4; i++) {
#pragma unroll
        for (int j = 0; j < 2; j++) {
            wmma::store_matrix_sync(stage, acc[i][j], 16, wmma::mem_row_major);
            __syncwarp();
            const int grow = bm + wm * 64 + i * 16 + r;
            const int gcol = bn + wn * 32 + j * 16 + c0;
            float v[8];
            *(float4*)&v[0] = *(float4*)&stage[r * 16 + c0];
            *(float4*)&v[4] = *(float4*)&stage[r * 16 + c0 + 4];

            if (MODE == 0) {
                __align__(16) __nv_bfloat16 h8[8], l8[8];
#pragma unroll
                for (int q = 0; q < 8; q++) {
                    float t = v[q];
                    t = t * __fdividef(1.f, 1.f + __expf(-t));     // silu
                    h8[q] = __float2bfloat16(t);
                    l8[q] = __float2bfloat16(t - __bfloat162float(h8[q]));
                }
                *(uint4*)(Ch + (size_t)grow * NN + gcol) = *(uint4*)h8;
                *(uint4*)(Cl + (size_t)grow * NN + gcol) = *(uint4*)l8;
            } else {
#pragma unroll
                for (int q = 0; q < 8; q++) {
                    float t = v[q];
                    if (MODE == 1) t = aval * (t + bias[gcol + q]);
                    v[q] = t;
                }
                float* cp = Cf + (size_t)grow * NN + gcol;
                *(float4*)(cp)     = *(float4*)&v[0];
                *(float4*)(cp + 4) = *(float4*)&v[4];
            }
            __syncwarp();
        }
    }
}

// ---------------- sequential scan -------------------------------------------
// Wx pre-scaled by alpha. Writes outs as bf16 hi/lo planes + h_final.
__global__ __launch_bounds__(256, 1)
void scan_kernel(const float* __restrict__ Wx,
                 const float* __restrict__ h0,
                 __nv_bfloat16* __restrict__ oh,
                 __nv_bfloat16* __restrict__ ol,
                 float* __restrict__ h_final)
{
    const int b    = blockIdx.x;
    const int tid  = threadIdx.x;
    const int lane = tid & 31;
    const int warp = tid >> 5;

    __shared__ float red[2][8];

    float4 h = *(const float4*)(h0 + (size_t)b * DIM + tid * 4);

    const float* wxb = Wx + (size_t)b * TSTEPS * DIM;
    __nv_bfloat16* ohb = oh + (size_t)b * TSTEPS * DIM;
    __nv_bfloat16* olb = ol + (size_t)b * TSTEPS * DIM;

    float4 wx0 = *(const float4*)(wxb + (size_t)0 * DIM + tid * 4);
    float4 wx1 = *(const float4*)(wxb + (size_t)1 * DIM + tid * 4);

    for (int t = 0; t < TSTEPS; t++) {
        const int tn = (t + 2 < TSTEPS) ? (t + 2) : (TSTEPS - 1);
        float4 wxn = *(const float4*)(wxb + (size_t)tn * DIM + tid * 4);

        h.x += wx0.x; h.y += wx0.y; h.z += wx0.z; h.w += wx0.w;

        float ss = h.x * h.x;
        ss = fmaf(h.y, h.y, ss);
        ss = fmaf(h.z, h.z, ss);
        ss = fmaf(h.w, h.w, ss);
#pragma unroll
        for (int off = 16; off > 0; off >>= 1)
            ss += __shfl_xor_sync(0xffffffffu, ss, off);
        if (lane == 0) red[t & 1][warp] = ss;
        __syncthreads();

        float tot = (red[t & 1][0] + red[t & 1][1]) + (red[t & 1][2] + red[t & 1][3]);
        tot += (red[t & 1][4] + red[t & 1][5]) + (red[t & 1][6] + red[t & 1][7]);

        const float rstd = rsqrtf(tot * (1.0f / DIM) + EPS);
        h.x *= rstd; h.y *= rstd; h.z *= rstd; h.w *= rstd;

        float o[4];
        o[0] = h.x * h.x * __fdividef(1.f, 1.f + __expf(-h.x));
        o[1] = h.y * h.y * __fdividef(1.f, 1.f + __expf(-h.y));
        o[2] = h.z * h.z * __fdividef(1.f, 1.f + __expf(-h.z));
        o[3] = h.w * h.w * __fdividef(1.f, 1.f + __expf(-h.w));

        __align__(8) __nv_bfloat16 h4[4], l4[4];
#pragma unroll
        for (int q = 0; q < 4; q++) {
            h4[q] = __float2bfloat16(o[q]);
            l4[q] = __float2bfloat16(o[q] - __bfloat162float(h4[q]));
        }
        *(uint2*)(ohb + (size_t)t * DIM + tid * 4) = *(uint2*)h4;
        *(uint2*)(olb + (size_t)t * DIM + tid * 4) = *(uint2*)l4;

        wx0 = wx1;
        wx1 = wxn;
    }

    if (h_final)
        *(float4*)(h_final + (size_t)b * DIM + tid * 4) = h;
}

// ---------------------------------------------------------------------------
extern "C" void kernel_launch(void* const* d_in, const int* in_sizes, int n_in,
                              void* d_out, int out_size)
{
    const float* x         = (const float*)d_in[0];
    const float* h0        = (const float*)d_in[1];
    const float* W_in      = (const float*)d_in[2];
    const float* W_cell    = (const float*)d_in[3];
    const float* b_cell    = (const float*)d_in[4];
    const float* log_alpha = (const float*)d_in[5];
    const float* W_out     = (const float*)d_in[6];

    float* y = (float*)d_out;
    float* h_final = nullptr;
    if ((size_t)out_size >= (size_t)MM * DIM + (size_t)BATCH * DIM)
        h_final = y + (size_t)MM * DIM;

    float* wx = nullptr;
    __nv_bfloat16 *xh, *xl, *aph, *apl, *oh, *ol, *wih, *wil, *wch, *wcl, *woh, *wol;
    cudaGetSymbolAddress((void**)&wx,  g_wx);
    cudaGetSymbolAddress((void**)&xh,  g_xh);  cudaGetSymbolAddress((void**)&xl,  g_xl);
    cudaGetSymbolAddress((void**)&aph, g_aph); cudaGetSymbolAddress((void**)&apl, g_apl);
    cudaGetSymbolAddress((void**)&oh,  g_oh);  cudaGetSymbolAddress((void**)&ol,  g_ol);
    cudaGetSymbolAddress((void**)&wih, g_wih); cudaGetSymbolAddress((void**)&wil, g_wil);
    cudaGetSymbolAddress((void**)&wch, g_wch); cudaGetSymbolAddress((void**)&wcl, g_wcl);
    cudaGetSymbolAddress((void**)&woh, g_woh); cudaGetSymbolAddress((void**)&wol, g_wol);

    static bool attr_done = false;
    if (!attr_done) {
        cudaFuncSetAttribute(gemm_bf16<0>, cudaFuncAttributeMaxDynamicSharedMemorySize, GEMM_SMEM);
        cudaFuncSetAttribute(gemm_bf16<1>, cudaFuncAttributeMaxDynamicSharedMemorySize, GEMM_SMEM);
        cudaFuncSetAttribute(gemm_bf16<2>, cudaFuncAttributeMaxDynamicSharedMemorySize, GEMM_SMEM);
        attr_done = true;
    }

    // one-time splits
    {
        int n8 = MM * KK / 8;
        split_fp32<<<(n8 + 255) / 256, 256>>>(x, xh, xl, n8);
        int w8 = NN * KK / 8;
        split_fp32<<<(w8 + 255) / 256, 256>>>(W_in,   wih, wil, w8);
        split_fp32<<<(w8 + 255) / 256, 256>>>(W_cell, wch, wcl, w8);
        split_fp32<<<(w8 + 255) / 256, 256>>>(W_out,  woh, wol, w8);
    }

    dim3 grid(NN / BN, MM / BM);
    dim3 block(256);

    // GEMM1: xp = silu(x @ W_in^T)  -> bf16 hi/lo planes
    gemm_bf16<0><<<grid, block, GEMM_SMEM>>>(xh, xl, wih, wil, nullptr, nullptr,
                                             nullptr, aph, apl);
    // GEMM2: wx = alpha*(xp @ W_cell^T + b_cell) -> fp32
    gemm_bf16<1><<<grid, block, GEMM_SMEM>>>(aph, apl, wch, wcl, b_cell, log_alpha,
                                             wx, nullptr, nullptr);
    // Scan -> outs hi/lo planes + h_final
    scan_kernel<<<BATCH, 256>>>(wx, h0, oh, ol, h_final);
    // GEMM3: y = outs @ W_out^T -> fp32
    gemm_bf16<2><<<grid, block, GEMM_SMEM>>>(oh, ol, woh, wol, nullptr, nullptr,
                                             y, nullptr, nullptr);
}

// round 6
// speedup vs baseline: 1.7890x; 1.0380x over previous
#include <cuda_runtime.h>
#include <cuda_bf16.h>
#include <mma.h>
#include <math.h>
#include <stdint.h>

using namespace nvcuda;

#define BATCH 8
#define TSTEPS 2048
#define DIM 1024
#define MM (BATCH * TSTEPS)   // 16384 rows
#define NN 1024
#define KK 1024
#define EPS 1e-6f

// ---------------- device-global scratch (allocation-free) -------------------
__device__ float         g_wx [(size_t)MM * NN];   // fp32 scan input
__device__ __nv_bfloat16 g_xh [(size_t)MM * KK], g_xl [(size_t)MM * KK];   // split(x)
__device__ __nv_bfloat16 g_aph[(size_t)MM * KK], g_apl[(size_t)MM * KK];   // split(xp)
__device__ __nv_bfloat16 g_oh [(size_t)MM * KK], g_ol [(size_t)MM * KK];   // split(outs)
__device__ __nv_bfloat16 g_wih[(size_t)NN * KK], g_wil[(size_t)NN * KK];
__device__ __nv_bfloat16 g_wch[(size_t)NN * KK], g_wcl[(size_t)NN * KK];
__device__ __nv_bfloat16 g_woh[(size_t)NN * KK], g_wol[(size_t)NN * KK];

// ---------------- fp32 -> bf16 hi/lo split (one-time) -----------------------
__global__ void split_fp32(const float* __restrict__ s,
                           __nv_bfloat16* __restrict__ hi,
                           __nv_bfloat16* __restrict__ lo, int n8)
{
    int i = blockIdx.x * blockDim.x + threadIdx.x;
    if (i >= n8) return;
    const float4* p = (const float4*)s + (size_t)i * 2;
    float4 a = p[0], b = p[1];
    float v[8] = {a.x, a.y, a.z, a.w, b.x, b.y, b.z, b.w};
    __align__(16) __nv_bfloat16 h[8], l[8];
#pragma unroll
    for (int q = 0; q < 8; q++) {
        h[q] = __float2bfloat16(v[q]);
        l[q] = __float2bfloat16(v[q] - __bfloat162float(h[q]));
    }
    *(uint4*)(hi + (size_t)i * 8) = *(uint4*)h;
    *(uint4*)(lo + (size_t)i * 8) = *(uint4*)l;
}

// ---------------- cp.async helpers ------------------------------------------
__device__ __forceinline__ void cp_async_16(void* smem, const void* gmem)
{
    uint32_t s = (uint32_t)__cvta_generic_to_shared(smem);
    asm volatile("cp.async.ca.shared.global [%0], [%1], 16;\n" :: "r"(s), "l"(gmem));
}
__device__ __forceinline__ void cp_commit()
{
    asm volatile("cp.async.commit_group;\n" ::: "memory");
}
template <int N>
__device__ __forceinline__ void cp_wait()
{
    asm volatile("cp.async.wait_group %0;\n" :: "n"(N) : "memory");
}

// ---------------- pipelined bf16 3-pass GEMM --------------------------------
#define BM 128
#define BN 128
#define BK 32
#define LDT 40                       // smem row stride in bf16 elems (80B)
#define QUAD (BM * LDT * 2)          // 10240 B per quadrant tile
#define STAGE_BYTES (4 * QUAD)       // 40960 B
#define STAGES 4
#define GEMM_SMEM (STAGES * STAGE_BYTES)   // 163840 B

__device__ __forceinline__ void load_quad(const __nv_bfloat16* __restrict__ gplane,
                                          int grow0, int k0, char* sq, int tid)
{
#pragma unroll
    for (int i = 0; i < 2; i++) {
        int c   = tid + i * 256;       // 0..511
        int row = c >> 2;              // 0..127
        int cb  = c & 3;               // 16B chunk within 64B row
        const __nv_bfloat16* g = gplane + (size_t)(grow0 + row) * KK + k0 + cb * 8;
        cp_async_16(sq + row * (LDT * 2) + cb * 16, g);
    }
}

template <int MODE>
__global__ __launch_bounds__(256, 1)
void gemm_bf16(const __nv_bfloat16* __restrict__ Ah_, const __nv_bfloat16* __restrict__ Al_,
               const __nv_bfloat16* __restrict__ Bh_, const __nv_bfloat16* __restrict__ Bl_,
               const float* __restrict__ bias, const float* __restrict__ log_alpha,
               float* __restrict__ Cf,
               __nv_bfloat16* __restrict__ Ch, __nv_bfloat16* __restrict__ Cl)
{
    extern __shared__ __align__(16) char dsm[];

    const int tid  = threadIdx.x;
    const int wid  = tid >> 5;
    const int lane = tid & 31;
    const int bm   = blockIdx.y * BM;
    const int bn   = blockIdx.x * BN;

    const int wm = wid & 1;   // 64-row slab
    const int wn = wid >> 1;  // 32-col slab

    wmma::fragment<wmma::accumulator, 16, 16, 16, float> acc[4][2];
#pragma unroll
    for (int i = 0; i < 4; i++)
#pragma unroll
        for (int j = 0; j < 2; j++) wmma::fill_fragment(acc[i][j], 0.0f);

    const int NT = KK / BK;   // 32 tiles

    // prologue: fill stages 0..STAGES-2
#pragma unroll
    for (int s = 0; s < STAGES - 1; s++) {
        char* p = dsm + s * STAGE_BYTES;
        load_quad(Ah_, bm, s * BK, p,            tid);
        load_quad(Al_, bm, s * BK, p + QUAD,     tid);
        load_quad(Bh_, bn, s * BK, p + 2 * QUAD, tid);
        load_quad(Bl_, bn, s * BK, p + 3 * QUAD, tid);
        cp_commit();
    }

    for (int t = 0; t < NT; t++) {
        cp_wait<STAGES - 2>();
        __syncthreads();

        // refill freed stage FIRST — maximizes load/compute overlap
        if (t + STAGES - 1 < NT) {
            const int tn = t + STAGES - 1;
            char* pn = dsm + (tn % STAGES) * STAGE_BYTES;
            load_quad(Ah_, bm, tn * BK, pn,            tid);
            load_quad(Al_, bm, tn * BK, pn + QUAD,     tid);
            load_quad(Bh_, bn, tn * BK, pn + 2 * QUAD, tid);
            load_quad(Bl_, bn, tn * BK, pn + 3 * QUAD, tid);
        }
        cp_commit();

        char* p = dsm + (t % STAGES) * STAGE_BYTES;
        const __nv_bfloat16* Ah = (const __nv_bfloat16*)p;
        const __nv_bfloat16* Al = (const __nv_bfloat16*)(p + QUAD);
        const __nv_bfloat16* Bh = (const __nv_bfloat16*)(p + 2 * QUAD);
        const __nv_bfloat16* Bl = (const __nv_bfloat16*)(p + 3 * QUAD);

#pragma unroll
        for (int ks = 0; ks < BK; ks += 16) {
            wmma::fragment<wmma::matrix_a, 16, 16, 16, __nv_bfloat16, wmma::row_major> fah[4], fal[4];
            wmma::fragment<wmma::matrix_b, 16, 16, 16, __nv_bfloat16, wmma::col_major> fbh[2], fbl[2];
#pragma unroll
            for (int i = 0; i < 4; i++) {
                const int row = wm * 64 + i * 16;
                wmma::load_matrix_sync(fah[i], Ah + row * LDT + ks, LDT);
                wmma::load_matrix_sync(fal[i], Al + row * LDT + ks, LDT);
            }
#pragma unroll
            for (int j = 0; j < 2; j++) {
                const int col = wn * 32 + j * 16;
                wmma::load_matrix_sync(fbh[j], Bh + col * LDT + ks, LDT);
                wmma::load_matrix_sync(fbl[j], Bl + col * LDT + ks, LDT);
            }
#pragma unroll
            for (int i = 0; i < 4; i++)
#pragma unroll
                for (int j = 0; j < 2; j++) {
                    wmma::mma_sync(acc[i][j], fah[i], fbl[j], acc[i][j]);
                    wmma::mma_sync(acc[i][j], fal[i], fbh[j], acc[i][j]);
                    wmma::mma_sync(acc[i][j], fah[i], fbh[j], acc[i][j]);
                }
        }
    }
    __syncthreads();

    // ---- epilogue: per-warp smem staging ----
    float aval = 0.f;
    if (MODE == 1) aval = __expf(log_alpha[0]);
    float* stage = (float*)dsm + wid * 256;   // 16x16 fp32 per warp

    const int r  = lane >> 1;
    const int c0 = (lane & 1) * 8;
#pragma unroll
    for (int i = 0; i < 4; i++) {
#pragma unroll
        for (int j = 0; j < 2; j++) {
            wmma::store_matrix_sync(stage, acc[i][j], 16, wmma::mem_row_major);
            __syncwarp();
            const int grow = bm + wm * 64 + i * 16 + r;
            const int gcol = bn + wn * 32 + j * 16 + c0;
            float v[8];
            *(float4*)&v[0] = *(float4*)&stage[r * 16 + c0];
            *(float4*)&v[4] = *(float4*)&stage[r * 16 + c0 + 4];

            if (MODE == 0) {
                __align__(16) __nv_bfloat16 h8[8], l8[8];
#pragma unroll
                for (int q = 0; q < 8; q++) {
                    float t = v[q];
                    t = t * __fdividef(1.f, 1.f + __expf(-t));     // silu
                    h8[q] = __float2bfloat16(t);
                    l8[q] = __float2bfloat16(t - __bfloat162float(h8[q]));
                }
                *(uint4*)(Ch + (size_t)grow * NN + gcol) = *(uint4*)h8;
                *(uint4*)(Cl + (size_t)grow * NN + gcol) = *(uint4*)l8;
            } else {
#pragma unroll
                for (int q = 0; q < 8; q++) {
                    float t = v[q];
                    if (MODE == 1) t = aval * (t + bias[gcol + q]);
                    v[q] = t;
                }
                float* cp = Cf + (size_t)grow * NN + gcol;
                *(float4*)(cp)     = *(float4*)&v[0];
                *(float4*)(cp + 4) = *(float4*)&v[4];
            }
            __syncwarp();
        }
    }
}

// ---------------- sequential scan -------------------------------------------
// Wx pre-scaled by alpha. Output (silu + bf16 split + store) deferred one step
// so it overlaps the next step's shuffle-reduction latency. Prefetch dist 4.
__global__ __launch_bounds__(256, 1)
void scan_kernel(const float* __restrict__ Wx,
                 const float* __restrict__ h0,
                 __nv_bfloat16* __restrict__ oh,
                 __nv_bfloat16* __restrict__ ol,
                 float* __restrict__ h_final)
{
    const int b    = blockIdx.x;
    const int tid  = threadIdx.x;
    const int lane = tid & 31;
    const int warp = tid >> 5;

    __shared__ float red[2][8];

    float4 h = *(const float4*)(h0 + (size_t)b * DIM + tid * 4);

    const float* wxb = Wx + (size_t)b * TSTEPS * DIM;
    __nv_bfloat16* ohb = oh + (size_t)b * TSTEPS * DIM;
    __nv_bfloat16* olb = ol + (size_t)b * TSTEPS * DIM;

    float4 w0 = *(const float4*)(wxb + (size_t)0 * DIM + tid * 4);
    float4 w1 = *(const float4*)(wxb + (size_t)1 * DIM + tid * 4);
    float4 w2 = *(const float4*)(wxb + (size_t)2 * DIM + tid * 4);
    float4 w3 = *(const float4*)(wxb + (size_t)3 * DIM + tid * 4);

    float4 hp = make_float4(0.f, 0.f, 0.f, 0.f);   // deferred h of step t-1

#pragma unroll 2
    for (int t = 0; t < TSTEPS; t++) {
        const int tn = (t + 4 < TSTEPS) ? (t + 4) : (TSTEPS - 1);
        float4 wxn = *(const float4*)(wxb + (size_t)tn * DIM + tid * 4);

        h.x += w0.x; h.y += w0.y; h.z += w0.z; h.w += w0.w;

        float ss = h.x * h.x;
        ss = fmaf(h.y, h.y, ss);
        ss = fmaf(h.z, h.z, ss);
        ss = fmaf(h.w, h.w, ss);

        // ---- deferred output of step t-1: fills the shfl-latency shadow ----
        if (t > 0) {
            float o[4];
            o[0] = hp.x * hp.x * __fdividef(1.f, 1.f + __expf(-hp.x));
            o[1] = hp.y * hp.y * __fdividef(1.f, 1.f + __expf(-hp.y));
            o[2] = hp.z * hp.z * __fdividef(1.f, 1.f + __expf(-hp.z));
            o[3] = hp.w * hp.w * __fdividef(1.f, 1.f + __expf(-hp.w));
            __align__(8) __nv_bfloat16 h4[4], l4[4];
#pragma unroll
            for (int q = 0; q < 4; q++) {
                h4[q] = __float2bfloat16(o[q]);
                l4[q] = __float2bfloat16(o[q] - __bfloat162float(h4[q]));
            }
            *(uint2*)(ohb + (size_t)(t - 1) * DIM + tid * 4) = *(uint2*)h4;
            *(uint2*)(olb + (size_t)(t - 1) * DIM + tid * 4) = *(uint2*)l4;
        }

#pragma unroll
        for (int off = 16; off > 0; off >>= 1)
            ss += __shfl_xor_sync(0xffffffffu, ss, off);
        if (lane == 0) red[t & 1][warp] = ss;
        __syncthreads();

        float tot = (red[t & 1][0] + red[t & 1][1]) + (red[t & 1][2] + red[t & 1][3]);
        tot += (red[t & 1][4] + red[t & 1][5]) + (red[t & 1][6] + red[t & 1][7]);

        const float rstd = rsqrtf(tot * (1.0f / DIM) + EPS);
        h.x *= rstd; h.y *= rstd; h.z *= rstd; h.w *= rstd;

        hp = h;
        w0 = w1; w1 = w2; w2 = w3; w3 = wxn;
    }

    // final deferred output (t = TSTEPS-1)
    {
        float o[4];
        o[0] = hp.x * hp.x * __fdividef(1.f, 1.f + __expf(-hp.x));
        o[1] = hp.y * hp.y * __fdividef(1.f, 1.f + __expf(-hp.y));
        o[2] = hp.z * hp.z * __fdividef(1.f, 1.f + __expf(-hp.z));
        o[3] = hp.w * hp.w * __fdividef(1.f, 1.f + __expf(-hp.w));
        __align__(8) __nv_bfloat16 h4[4], l4[4];
#pragma unroll
        for (int q = 0; q < 4; q++) {
            h4[q] = __float2bfloat16(o[q]);
            l4[q] = __float2bfloat16(o[q] - __bfloat162float(h4[q]));
        }
        *(uint2*)(ohb + (size_t)(TSTEPS - 1) * DIM + tid * 4) = *(uint2*)h4;
        *(uint2*)(olb + (size_t)(TSTEPS - 1) * DIM + tid * 4) = *(uint2*)l4;
    }

    if (h_final)
        *(float4*)(h_final + (size_t)b * DIM + tid * 4) = h;
}

// ---------------------------------------------------------------------------
extern "C" void kernel_launch(void* const* d_in, const int* in_sizes, int n_in,
                              void* d_out, int out_size)
{
    const float* x         = (const float*)d_in[0];
    const float* h0        = (const float*)d_in[1];
    const float* W_in      = (const float*)d_in[2];
    const float* W_cell    = (const float*)d_in[3];
    const float* b_cell    = (const float*)d_in[4];
    const float* log_alpha = (const float*)d_in[5];
    const float* W_out     = (const float*)d_in[6];

    float* y = (float*)d_out;
    float* h_final = nullptr;
    if ((size_t)out_size >= (size_t)MM * DIM + (size_t)BATCH * DIM)
        h_final = y + (size_t)MM * DIM;

    float* wx = nullptr;
    __nv_bfloat16 *xh, *xl, *aph, *apl, *oh, *ol, *wih, *wil, *wch, *wcl, *woh, *wol;
    cudaGetSymbolAddress((void**)&wx,  g_wx);
    cudaGetSymbolAddress((void**)&xh,  g_xh);  cudaGetSymbolAddress((void**)&xl,  g_xl);
    cudaGetSymbolAddress((void**)&aph, g_aph); cudaGetSymbolAddress((void**)&apl, g_apl);
    cudaGetSymbolAddress((void**)&oh,  g_oh);  cudaGetSymbolAddress((void**)&ol,  g_ol);
    cudaGetSymbolAddress((void**)&wih, g_wih); cudaGetSymbolAddress((void**)&wil, g_wil);
    cudaGetSymbolAddress((void**)&wch, g_wch); cudaGetSymbolAddress((void**)&wcl, g_wcl);
    cudaGetSymbolAddress((void**)&woh, g_woh); cudaGetSymbolAddress((void**)&wol, g_wol);

    static bool attr_done = false;
    if (!attr_done) {
        cudaFuncSetAttribute(gemm_bf16<0>, cudaFuncAttributeMaxDynamicSharedMemorySize, GEMM_SMEM);
        cudaFuncSetAttribute(gemm_bf16<1>, cudaFuncAttributeMaxDynamicSharedMemorySize, GEMM_SMEM);
        cudaFuncSetAttribute(gemm_bf16<2>, cudaFuncAttributeMaxDynamicSharedMemorySize, GEMM_SMEM);
        attr_done = true;
    }

    // one-time splits
    {
        int n8 = MM * KK / 8;
        split_fp32<<<(n8 + 255) / 256, 256>>>(x, xh, xl, n8);
        int w8 = NN * KK / 8;
        split_fp32<<<(w8 + 255) / 256, 256>>>(W_in,   wih, wil, w8);
        split_fp32<<<(w8 + 255) / 256, 256>>>(W_cell, wch, wcl, w8);
        split_fp32<<<(w8 + 255) / 256, 256>>>(W_out,  woh, wol, w8);
    }

    dim3 grid(NN / BN, MM / BM);
    dim3 block(256);

    // GEMM1: xp = silu(x @ W_in^T)  -> bf16 hi/lo planes
    gemm_bf16<0><<<grid, block, GEMM_SMEM>>>(xh, xl, wih, wil, nullptr, nullptr,
                                             nullptr, aph, apl);
    // GEMM2: wx = alpha*(xp @ W_cell^T + b_cell) -> fp32
    gemm_bf16<1><<<grid, block, GEMM_SMEM>>>(aph, apl, wch, wcl, b_cell, log_alpha,
                                             wx, nullptr, nullptr);
    // Scan -> outs hi/lo planes + h_final
    scan_kernel<<<BATCH, 256>>>(wx, h0, oh, ol, h_final);
    // GEMM3: y = outs @ W_out^T -> fp32
    gemm_bf16<2><<<grid, block, GEMM_SMEM>>>(oh, ol, woh, wol, nullptr, nullptr,
                                             y, nullptr, nullptr);
}